// round 1
// baseline (speedup 1.0000x reference)
#include <cuda_runtime.h>
#include <cuda_bf16.h>
#include <math.h>
#include <float.h>

// Problem constants
#define BB 2
#define MM 256
#define DD 256
#define DE 64
#define TP 257   // M+1 tokens

// ---------------- scratch (device globals; no allocs allowed) ----------------
__device__ float g_WzT [DD*DD];    // [k][d] = Wz[d][k]
__device__ float g_WmfT[DD*DD];    // [k][d] = Wm[d][DE+k]
__device__ float g_WmdT[DE*DD];    // [e][d] = Wm[d][e]
__device__ float g_Wh1T[DD*DD];    // [j][d] = Wh[d][j]
__device__ float g_Wh2T[DD*DD];    // [k][d] = Wh[d][DD+k]
__device__ float g_nfproj[BB*MM*DD];
__device__ float g_asph  [MM*DD];
__device__ float g_nfdot [BB*MM];
__device__ float g_aspdot[MM];

// ---------------- K0: weight transposes ----------------
__global__ void k0_transpose(const float* __restrict__ Wz,
                             const float* __restrict__ Wm,
                             const float* __restrict__ Wh)
{
    int idx = blockIdx.x * blockDim.x + threadIdx.x; // 65536 threads exactly
    int k = idx >> 8;
    int d = idx & 255;
    g_WzT [idx] = Wz[d*DD + k];
    g_WmfT[idx] = Wm[d*(DE+DD) + DE + k];
    g_Wh1T[idx] = Wh[d*(2*DD) + k];
    g_Wh2T[idx] = Wh[d*(2*DD) + DD + k];
    if (k < DE) g_WmdT[k*DD + d] = Wm[d*(DE+DD) + k];
}

// ---------------- block reduction helpers ----------------
__device__ __forceinline__ float block_sum(float v, float* red) {
    #pragma unroll
    for (int o = 16; o > 0; o >>= 1) v += __shfl_down_sync(0xffffffffu, v, o);
    if ((threadIdx.x & 31) == 0) red[threadIdx.x >> 5] = v;
    __syncthreads();
    if (threadIdx.x < 8) {
        v = red[threadIdx.x];
        #pragma unroll
        for (int o = 4; o > 0; o >>= 1) v += __shfl_down_sync(0xffu, v, o);
        if (threadIdx.x == 0) red[0] = v;
    }
    __syncthreads();
    float r = red[0];
    __syncthreads();
    return r;
}

__device__ __forceinline__ float block_max(float v, float* red) {
    #pragma unroll
    for (int o = 16; o > 0; o >>= 1) v = fmaxf(v, __shfl_down_sync(0xffffffffu, v, o));
    if ((threadIdx.x & 31) == 0) red[threadIdx.x >> 5] = v;
    __syncthreads();
    if (threadIdx.x < 8) {
        v = red[threadIdx.x];
        #pragma unroll
        for (int o = 4; o > 0; o >>= 1) v = fmaxf(v, __shfl_down_sync(0xffu, v, o));
        if (threadIdx.x == 0) red[0] = v;
    }
    __syncthreads();
    float r = red[0];
    __syncthreads();
    return r;
}

// ---------------- K1: zf rows -> nfdot / aspdot / nf_proj / asp_h ----------------
// grid: (64, 2) — 4 token rows per block, 256 threads
__global__ void k1_proj(const float* __restrict__ features,
                        const float* __restrict__ bz,
                        const float* __restrict__ Wa)
{
    const int b  = blockIdx.y;
    const int m0 = blockIdx.x * 4;
    const int d  = threadIdx.x;

    __shared__ float xs[4][DD];
    __shared__ float fs[4][DD];
    __shared__ float red[8];

    #pragma unroll
    for (int g = 0; g < 4; g++)
        xs[g][d] = features[((size_t)b*TP + m0 + g + 1)*DD + d];
    __syncthreads();

    // zf = x @ Wz^T + bz
    float a0 = bz[d], a1 = a0, a2 = a0, a3 = a0;
    for (int k = 0; k < DD; k++) {
        float w = g_WzT[k*DD + d];
        a0 = fmaf(xs[0][k], w, a0);
        a1 = fmaf(xs[1][k], w, a1);
        a2 = fmaf(xs[2][k], w, a2);
        a3 = fmaf(xs[3][k], w, a3);
    }
    fs[0][d] = a0; fs[1][d] = a1; fs[2][d] = a2; fs[3][d] = a3;
    __syncthreads();

    // nfdot / aspdot
    const float wnf  = Wa[DE + d];
    const float wasp = Wa[DE + DD + d];
    #pragma unroll
    for (int g = 0; g < 4; g++) {
        float tot = block_sum(fs[g][d] * wnf, red);
        if (d == 0) g_nfdot[b*MM + m0 + g] = tot;
        if (b == 0) {
            float t2 = block_sum(fs[g][d] * wasp, red);
            if (d == 0) g_aspdot[m0 + g] = t2;
        }
    }

    // nf_proj = f @ Wm_f^T
    float p0 = 0.f, p1 = 0.f, p2 = 0.f, p3 = 0.f;
    for (int k = 0; k < DD; k++) {
        float w = g_WmfT[k*DD + d];
        p0 = fmaf(fs[0][k], w, p0);
        p1 = fmaf(fs[1][k], w, p1);
        p2 = fmaf(fs[2][k], w, p2);
        p3 = fmaf(fs[3][k], w, p3);
    }
    g_nfproj[((size_t)b*MM + m0 + 0)*DD + d] = p0;
    g_nfproj[((size_t)b*MM + m0 + 1)*DD + d] = p1;
    g_nfproj[((size_t)b*MM + m0 + 2)*DD + d] = p2;
    g_nfproj[((size_t)b*MM + m0 + 3)*DD + d] = p3;

    // asp_h = asp @ Wh2^T (batch 0 only)
    if (b == 0) {
        float q0 = 0.f, q1 = 0.f, q2 = 0.f, q3 = 0.f;
        for (int k = 0; k < DD; k++) {
            float w = g_Wh2T[k*DD + d];
            q0 = fmaf(fs[0][k], w, q0);
            q1 = fmaf(fs[1][k], w, q1);
            q2 = fmaf(fs[2][k], w, q2);
            q3 = fmaf(fs[3][k], w, q3);
        }
        g_asph[(m0 + 0)*DD + d] = q0;
        g_asph[(m0 + 1)*DD + d] = q1;
        g_asph[(m0 + 2)*DD + d] = q2;
        g_asph[(m0 + 3)*DD + d] = q3;
    }
}

// ---------------- K2: sparse attention + message + output head ----------------
// grid: 32 blocks (b in [0,2), slot in [0,16)), 256 threads
__global__ void k2_attn(const float* __restrict__ dep,
                        const int*   __restrict__ adj,
                        const int*   __restrict__ asp_start,
                        const int*   __restrict__ asp_end,
                        const float* __restrict__ Wa,
                        float*       __restrict__ out)
{
    const int b    = blockIdx.x >> 4;
    const int slot = blockIdx.x & 15;
    const int st = asp_start[b];
    const int en = asp_end[b];
    const int i  = st + slot;
    if (i >= en || i >= MM) return;

    const int d = threadIdx.x;

    __shared__ float s_s[2*MM];
    __shared__ float w_s[2*MM];
    __shared__ int   list[2*MM];
    __shared__ int   cnt;
    __shared__ float ds[DE];
    __shared__ float red[8];
    __shared__ float fused[DD];
    __shared__ float wdep[DE];

    if (d == 0) cnt = 0;
    if (d < DE) wdep[d] = Wa[d];
    __syncthreads();

    const float aspdot_i = g_aspdot[i];
    float lmax = -FLT_MAX;

    // ---- Phase A: masked scores + compact valid-key list ----
    #pragma unroll
    for (int h = 0; h < 2; h++) {
        const int k = d + h*MM;
        int msk;
        const float* dv;
        if (h == 0) {
            msk = adj[((size_t)b*MM + i)*MM + k];
            dv  = &dep[(((size_t)b*MM + i)*MM + k)*DE];
        } else {
            msk = adj[((size_t)b*MM + (k - MM))*MM + i];
            dv  = &dep[(((size_t)b*MM + (k - MM))*MM + i)*DE];
        }
        float sv = -FLT_MAX;
        if (msk != 0) {
            int pos = atomicAdd(&cnt, 1);
            list[pos] = k;
            const float4* dv4 = reinterpret_cast<const float4*>(dv);
            float acc = 0.f;
            #pragma unroll
            for (int e4 = 0; e4 < DE/4; e4++) {
                float4 v = dv4[e4];
                acc = fmaf(v.x, wdep[4*e4+0], acc);
                acc = fmaf(v.y, wdep[4*e4+1], acc);
                acc = fmaf(v.z, wdep[4*e4+2], acc);
                acc = fmaf(v.w, wdep[4*e4+3], acc);
            }
            float s0 = acc + g_nfdot[b*MM + (k & (MM-1))] + aspdot_i;
            sv = (s0 > 0.f) ? s0 : 0.01f * s0;   // leaky relu
            lmax = fmaxf(lmax, sv);
        }
        s_s[k] = sv;
    }
    __syncthreads();

    // ---- Phase B: softmax over valid keys ----
    const float smax = block_max(lmax, red);
    float lsum = 0.f;
    #pragma unroll
    for (int h = 0; h < 2; h++) {
        const int k = d + h*MM;
        float sv = s_s[k];
        float e  = (sv > -1e37f) ? expf(sv - smax) : 0.f;
        w_s[k] = e;
        lsum += e;
    }
    const float ssum = block_sum(lsum, red);
    const float inv  = 1.f / ssum;
    const int n = cnt;
    __syncthreads();

    // preload Wm_dep column for this d into registers (reused across all keys)
    float wmd[DE];
    #pragma unroll
    for (int e = 0; e < DE; e++) wmd[e] = g_WmdT[e*DD + d];

    // ---- Phase C: fused[d] = sum_k w_k * relu(dep_k @ Wm_dep^T + nf_proj) ----
    float acc = 0.f;
    for (int j = 0; j < n; j++) {
        const int k = list[j];
        __syncthreads();
        if (d < DE) {
            const float* dv = (k < MM)
                ? &dep[(((size_t)b*MM + i)*MM + k)*DE]
                : &dep[(((size_t)b*MM + (k - MM))*MM + i)*DE];
            ds[d] = dv[d];
        }
        __syncthreads();
        const float wk = w_s[k] * inv;
        float m = g_nfproj[((size_t)b*MM + (k & (MM-1)))*DD + d];
        #pragma unroll
        for (int e = 0; e < DE; e++) m = fmaf(ds[e], wmd[e], m);
        acc = fmaf(wk, fmaxf(m, 0.f), acc);
    }

    // ---- Phase D: out = relu(fused @ Wh1^T + asp_h[i]) ----
    fused[d] = acc;
    __syncthreads();
    float o = g_asph[i*DD + d];
    for (int j = 0; j < DD; j++)
        o = fmaf(fused[j], g_Wh1T[j*DD + d], o);
    out[((size_t)b*TP + 1 + i)*DD + d] = fmaxf(o, 0.f);
}

// ---------------- launcher ----------------
extern "C" void kernel_launch(void* const* d_in, const int* in_sizes, int n_in,
                              void* d_out, int out_size)
{
    const float* features  = (const float*)d_in[0];
    const float* dep       = (const float*)d_in[1];
    const int*   adj       = (const int*)  d_in[2];
    const int*   asp_start = (const int*)  d_in[3];
    const int*   asp_end   = (const int*)  d_in[4];
    const float* Wz        = (const float*)d_in[5];
    const float* bz        = (const float*)d_in[6];
    const float* Wa        = (const float*)d_in[7];
    const float* Wm        = (const float*)d_in[8];
    const float* Wh        = (const float*)d_in[9];
    float* out = (float*)d_out;

    // output starts as a copy of features (row 0 + all non-updated tokens)
    cudaMemcpyAsync(out, features, (size_t)BB*TP*DD*sizeof(float),
                    cudaMemcpyDeviceToDevice, 0);

    k0_transpose<<<256, 256>>>(Wz, Wm, Wh);
    k1_proj<<<dim3(MM/4, BB), 256>>>(features, bz, Wa);
    k2_attn<<<BB*16, 256>>>(dep, adj, asp_start, asp_end, Wa, out);
}

// round 3
// speedup vs baseline: 1.3545x; 1.3545x over previous
#include <cuda_runtime.h>
#include <math.h>
#include <float.h>

#define BB 2
#define MM 256
#define DD 256
#define DE 64
#define TP 257

// ---------------- scratch ----------------
__device__ float g_WzT [DD*DD];    // [k][d] = Wz[d][k]
__device__ float g_WmfT[DD*DD];    // [k][d] = Wm[d][DE+k]
__device__ float g_WmdT[DE*DD];    // [e][d] = Wm[d][e]
__device__ float g_Wh1T[DD*DD];    // [j][d] = Wh[d][j]
__device__ float g_Wh2T[DD*DD];    // [k][d] = Wh[d][DD+k]
__device__ float g_nfproj[BB*MM*DD];
__device__ float g_nfdot [BB*MM];
__device__ float g_f0[MM*DD];      // zf[0,1:] rows (asp)

// ---------------- k0: coalesced tiled transposes + out copy ----------------
__global__ __launch_bounds__(256) void k0(const float* __restrict__ Wz,
                                          const float* __restrict__ Wm,
                                          const float* __restrict__ Wh,
                                          const float* __restrict__ features,
                                          float* __restrict__ out)
{
    const int bid = blockIdx.x, tid = threadIdx.x;
    if (bid < 272) {
        const float* s; float* dst; int ss; int rtile, ctile;
        if (bid < 64)       { s = Wz;      dst = g_WzT;  ss = DD;    rtile = bid>>3;        ctile = bid&7; }
        else if (bid < 128) { s = Wm+DE;   dst = g_WmfT; ss = DE+DD; rtile = (bid-64)>>3;   ctile = (bid-64)&7; }
        else if (bid < 192) { s = Wh;      dst = g_Wh1T; ss = 2*DD;  rtile = (bid-128)>>3;  ctile = (bid-128)&7; }
        else if (bid < 256) { s = Wh+DD;   dst = g_Wh2T; ss = 2*DD;  rtile = (bid-192)>>3;  ctile = (bid-192)&7; }
        else                { s = Wm;      dst = g_WmdT; ss = DE+DD; rtile = (bid-256)>>1;  ctile = (bid-256)&1; }
        __shared__ float t[32][33];
        const int r0 = tid >> 5, c = tid & 31;
        #pragma unroll
        for (int i = 0; i < 4; i++) {
            int r = r0 + i*8;
            t[r][c] = s[(size_t)(rtile*32 + r)*ss + ctile*32 + c];
        }
        __syncthreads();
        #pragma unroll
        for (int i = 0; i < 4; i++) {
            int r = r0 + i*8;
            dst[(size_t)(ctile*32 + r)*DD + rtile*32 + c] = t[c][r];
        }
    } else {
        // copy features -> out (float4)
        const int cb = bid - 272;
        const float4* src = (const float4*)features;
        float4* d4 = (float4*)out;
        const int total = BB*TP*DD/4;  // 32896
        for (int x = cb*256 + tid; x < total; x += 64*256) d4[x] = src[x];
    }
}

// ---------------- reduction helpers ----------------
__device__ __forceinline__ float bsum256(float v, float* red) {
    #pragma unroll
    for (int o = 16; o > 0; o >>= 1) v += __shfl_down_sync(0xffffffffu, v, o);
    if ((threadIdx.x & 31) == 0) red[threadIdx.x >> 5] = v;
    __syncthreads();
    if (threadIdx.x < 8) {
        v = red[threadIdx.x];
        #pragma unroll
        for (int o = 4; o > 0; o >>= 1) v += __shfl_down_sync(0xffu, v, o);
        if (threadIdx.x == 0) red[0] = v;
    }
    __syncthreads();
    float r = red[0];
    __syncthreads();
    return r;
}

__device__ __forceinline__ float bsum512(float v, float* red) {
    #pragma unroll
    for (int o = 16; o > 0; o >>= 1) v += __shfl_down_sync(0xffffffffu, v, o);
    if ((threadIdx.x & 31) == 0) red[threadIdx.x >> 5] = v;
    __syncthreads();
    if (threadIdx.x < 16) {
        v = red[threadIdx.x];
        #pragma unroll
        for (int o = 8; o > 0; o >>= 1) v += __shfl_down_sync(0xffffu, v, o);
        if (threadIdx.x == 0) red[0] = v;
    }
    __syncthreads();
    float r = red[0];
    __syncthreads();
    return r;
}

__device__ __forceinline__ float bmax512(float v, float* red) {
    #pragma unroll
    for (int o = 16; o > 0; o >>= 1) v = fmaxf(v, __shfl_down_sync(0xffffffffu, v, o));
    if ((threadIdx.x & 31) == 0) red[threadIdx.x >> 5] = v;
    __syncthreads();
    if (threadIdx.x < 16) {
        v = red[threadIdx.x];
        #pragma unroll
        for (int o = 8; o > 0; o >>= 1) v = fmaxf(v, __shfl_down_sync(0xffffu, v, o));
        if (threadIdx.x == 0) red[0] = v;
    }
    __syncthreads();
    float r = red[0];
    __syncthreads();
    return r;
}

// ---------------- k1: zf + nfdot + nf_proj (+ f0 rows for batch 0) ----------------
__device__ __forceinline__ void matvec4(const float* __restrict__ wT, int d,
                                        const float (*xs)[DD],
                                        float& a0, float& a1, float& a2, float& a3)
{
    #pragma unroll 4
    for (int k = 0; k < DD; k += 4) {
        const float4 x0 = *reinterpret_cast<const float4*>(&xs[0][k]);
        const float4 x1 = *reinterpret_cast<const float4*>(&xs[1][k]);
        const float4 x2 = *reinterpret_cast<const float4*>(&xs[2][k]);
        const float4 x3 = *reinterpret_cast<const float4*>(&xs[3][k]);
        const float w0 = wT[(k+0)*DD + d];
        const float w1 = wT[(k+1)*DD + d];
        const float w2 = wT[(k+2)*DD + d];
        const float w3 = wT[(k+3)*DD + d];
        a0 = fmaf(x0.x, w0, a0); a0 = fmaf(x0.y, w1, a0); a0 = fmaf(x0.z, w2, a0); a0 = fmaf(x0.w, w3, a0);
        a1 = fmaf(x1.x, w0, a1); a1 = fmaf(x1.y, w1, a1); a1 = fmaf(x1.z, w2, a1); a1 = fmaf(x1.w, w3, a1);
        a2 = fmaf(x2.x, w0, a2); a2 = fmaf(x2.y, w1, a2); a2 = fmaf(x2.z, w2, a2); a2 = fmaf(x2.w, w3, a2);
        a3 = fmaf(x3.x, w0, a3); a3 = fmaf(x3.y, w1, a3); a3 = fmaf(x3.z, w2, a3); a3 = fmaf(x3.w, w3, a3);
    }
}

__global__ __launch_bounds__(256) void k1(const float* __restrict__ features,
                                          const float* __restrict__ bz,
                                          const float* __restrict__ Wa)
{
    const int b  = blockIdx.y;
    const int m0 = blockIdx.x * 4;
    const int d  = threadIdx.x;

    __shared__ __align__(16) float xs[4][DD];
    __shared__ __align__(16) float fs[4][DD];
    __shared__ float red[8];

    // load 4 rows (float4, coalesced)
    {
        const int g = threadIdx.x >> 6, q = threadIdx.x & 63;
        const float4* f4 = (const float4*)&features[((size_t)b*TP + m0 + 1 + g)*DD];
        ((float4*)xs[g])[q] = f4[q];
    }
    __syncthreads();

    // zf = x @ Wz^T + bz
    float a0 = bz[d], a1 = a0, a2 = a0, a3 = a0;
    matvec4(g_WzT, d, xs, a0, a1, a2, a3);
    fs[0][d] = a0; fs[1][d] = a1; fs[2][d] = a2; fs[3][d] = a3;
    __syncthreads();

    // nfdot[m] = f[m] . Wa[DE:DE+D]
    const float wnf = Wa[DE + d];
    #pragma unroll
    for (int g = 0; g < 4; g++) {
        float tot = bsum256(fs[g][d] * wnf, red);
        if (d == 0) g_nfdot[b*MM + m0 + g] = tot;
    }

    // nf_proj = f @ Wm_f^T
    float p0 = 0.f, p1 = 0.f, p2 = 0.f, p3 = 0.f;
    matvec4(g_WmfT, d, (const float(*)[DD])fs, p0, p1, p2, p3);
    g_nfproj[((size_t)b*MM + m0 + 0)*DD + d] = p0;
    g_nfproj[((size_t)b*MM + m0 + 1)*DD + d] = p1;
    g_nfproj[((size_t)b*MM + m0 + 2)*DD + d] = p2;
    g_nfproj[((size_t)b*MM + m0 + 3)*DD + d] = p3;

    // batch-0 zf rows for k2 (asp)
    if (b == 0) {
        g_f0[(m0 + 0)*DD + d] = fs[0][d];
        g_f0[(m0 + 1)*DD + d] = fs[1][d];
        g_f0[(m0 + 2)*DD + d] = fs[2][d];
        g_f0[(m0 + 3)*DD + d] = fs[3][d];
    }
}

// ---------------- k2: sparse attention + message + output head ----------------
// grid 32 (b*16 + slot), 512 threads
__global__ __launch_bounds__(512) void k2(const float* __restrict__ dep,
                                          const int*   __restrict__ adj,
                                          const int*   __restrict__ asp_start,
                                          const int*   __restrict__ asp_end,
                                          const float* __restrict__ Wa,
                                          float*       __restrict__ out)
{
    const int b    = blockIdx.x >> 4;
    const int slot = blockIdx.x & 15;
    const int st = asp_start[b];
    const int en = asp_end[b];
    const int i  = st + slot;
    if (i >= en || i >= MM) return;

    const int tid = threadIdx.x;
    const int d   = tid & 255;   // 0..255
    const int g   = tid >> 8;    // 0..1 (half-block id)

    __shared__ __align__(16) float s_s[2*MM];
    __shared__ __align__(16) float w_s[2*MM];
    __shared__ __align__(16) int   list[2*MM];
    __shared__ __align__(16) float f0i[DD];
    __shared__ __align__(16) float wdep[DE];
    __shared__ __align__(16) float ds[2][2][DE];      // [buf][pair-member][e]
    __shared__ __align__(16) float fpart[2][DD];
    __shared__ __align__(16) float fused_s[DD];
    __shared__ __align__(16) float opart[2][DD];
    __shared__ float red[16];
    __shared__ int   cnt;

    if (tid == 0) cnt = 0;
    if (tid < DE) wdep[tid] = Wa[tid];
    if (tid < DD) f0i[tid] = g_f0[i*DD + tid];
    __syncthreads();

    // aspdot_i = asp[i] . Wa[DE+D:]
    float av = (tid < DD) ? f0i[tid] * Wa[DE + DD + tid] : 0.f;
    const float aspdot_i = bsum512(av, red);

    // ---- Phase A: masked scores, one candidate per thread ----
    const int k = tid;
    float sv = -FLT_MAX;
    {
        int msk;
        const float* dv;
        if (k < MM) {
            msk = adj[((size_t)b*MM + i)*MM + k];
            dv  = &dep[(((size_t)b*MM + i)*MM + k)*DE];
        } else {
            msk = adj[((size_t)b*MM + (k - MM))*MM + i];
            dv  = &dep[(((size_t)b*MM + (k - MM))*MM + i)*DE];
        }
        if (msk != 0) {
            int pos = atomicAdd(&cnt, 1);
            list[pos] = k;
            const float4* dv4 = reinterpret_cast<const float4*>(dv);
            float acc = 0.f;
            #pragma unroll
            for (int e4 = 0; e4 < DE/4; e4++) {
                float4 v = dv4[e4];
                acc = fmaf(v.x, wdep[4*e4+0], acc);
                acc = fmaf(v.y, wdep[4*e4+1], acc);
                acc = fmaf(v.z, wdep[4*e4+2], acc);
                acc = fmaf(v.w, wdep[4*e4+3], acc);
            }
            float s0 = acc + g_nfdot[b*MM + (k & (MM-1))] + aspdot_i;
            sv = (s0 > 0.f) ? s0 : 0.01f * s0;
        }
        s_s[k] = sv;
    }
    __syncthreads();
    const int n = cnt;

    // ---- Phase B: softmax over valid keys ----
    const float smax = bmax512(sv, red);
    float e = (sv > -1e37f) ? expf(sv - smax) : 0.f;
    w_s[k] = e;
    const float ssum = bsum512(e, red);
    const float inv  = 1.f / ssum;

    // ---- Phase C: fused[d] = sum_k w_k * relu(dep_k @ Wm_dep^T + nf_proj[k]) ----
    float wmd[DE];
    #pragma unroll
    for (int ee = 0; ee < DE; ee++) wmd[ee] = g_WmdT[ee*DD + d];

    const int li = tid >> 6;     // 0/1 : which pair member this loader serves
    const int le = tid & 63;     // element within dep row

    // stage pair 0
    if (tid < 128) {
        float r0 = 0.f;
        if (li < n) {
            int kk = list[li];
            const float* p = (kk < MM)
                ? &dep[(((size_t)b*MM + i)*MM + kk)*DE]
                : &dep[(((size_t)b*MM + (kk - MM))*MM + i)*DE];
            r0 = p[le];
        }
        ds[0][li][le] = r0;
    }

    float acc = 0.f;
    const int npairs = (n + 1) >> 1;
    for (int p = 0; p < npairs; p++) {
        // prefetch pair p+1 into registers
        float r = 0.f;
        if (tid < 128) {
            int jn = 2*(p+1) + li;
            if (jn < n) {
                int kk = list[jn];
                const float* pp = (kk < MM)
                    ? &dep[(((size_t)b*MM + i)*MM + kk)*DE]
                    : &dep[(((size_t)b*MM + (kk - MM))*MM + i)*DE];
                r = pp[le];
            }
        }
        __syncthreads();   // ds[p&1] (pair p) visible to all
        const int j = 2*p + g;
        if (j < n) {
            const int kk = list[j];
            const float wk = w_s[kk] * inv;
            float m = g_nfproj[((size_t)b*MM + (kk & (MM-1)))*DD + d];
            const float4* d4 = reinterpret_cast<const float4*>(ds[p & 1][g]);
            #pragma unroll
            for (int e4 = 0; e4 < DE/4; e4++) {
                float4 v = d4[e4];
                m = fmaf(v.x, wmd[4*e4+0], m);
                m = fmaf(v.y, wmd[4*e4+1], m);
                m = fmaf(v.z, wmd[4*e4+2], m);
                m = fmaf(v.w, wmd[4*e4+3], m);
            }
            acc = fmaf(wk, fmaxf(m, 0.f), acc);
        }
        __syncthreads();   // all reads of ds[(p+1)&1] from iter p-1 are done
        if (tid < 128) ds[(p + 1) & 1][li][le] = r;
    }

    fpart[g][d] = acc;
    __syncthreads();
    if (tid < DD) fused_s[tid] = fpart[0][tid] + fpart[1][tid];
    __syncthreads();

    // ---- Phase D: out[d] = relu( fused @ Wh1^T + asp[i] @ Wh2^T ) ----
    {
        const float* Wt = g ? g_Wh2T : g_Wh1T;
        const float* Xs = g ? f0i : fused_s;
        float o0 = 0.f, o1 = 0.f, o2 = 0.f, o3 = 0.f;
        #pragma unroll 4
        for (int j = 0; j < DD; j += 4) {
            o0 = fmaf(Xs[j+0], Wt[(j+0)*DD + d], o0);
            o1 = fmaf(Xs[j+1], Wt[(j+1)*DD + d], o1);
            o2 = fmaf(Xs[j+2], Wt[(j+2)*DD + d], o2);
            o3 = fmaf(Xs[j+3], Wt[(j+3)*DD + d], o3);
        }
        opart[g][d] = (o0 + o1) + (o2 + o3);
    }
    __syncthreads();
    if (tid < DD)
        out[((size_t)b*TP + 1 + i)*DD + tid] = fmaxf(opart[0][tid] + opart[1][tid], 0.f);
}

// ---------------- launcher ----------------
extern "C" void kernel_launch(void* const* d_in, const int* in_sizes, int n_in,
                              void* d_out, int out_size)
{
    const float* features  = (const float*)d_in[0];
    const float* dep       = (const float*)d_in[1];
    const int*   adj       = (const int*)  d_in[2];
    const int*   asp_start = (const int*)  d_in[3];
    const int*   asp_end   = (const int*)  d_in[4];
    const float* Wz        = (const float*)d_in[5];
    const float* bz        = (const float*)d_in[6];
    const float* Wa        = (const float*)d_in[7];
    const float* Wm        = (const float*)d_in[8];
    const float* Wh        = (const float*)d_in[9];
    float* out = (float*)d_out;

    k0<<<336, 256>>>(Wz, Wm, Wh, features, out);
    k1<<<dim3(64, 2), 256>>>(features, bz, Wa);
    k2<<<32, 512>>>(dep, adj, asp_start, asp_end, Wa, out);
}

// round 4
// speedup vs baseline: 1.8296x; 1.3507x over previous
#include <cuda_runtime.h>
#include <math.h>
#include <float.h>

#define BB 2
#define MM 256
#define DD 256
#define DE 64
#define TP 257

// ---------------- scratch ----------------
__device__ float g_WmdT  [DE*DD];      // [e][d] = Wm[d][e]
__device__ float g_nfproj[BB*MM*DD];
__device__ float g_nfdot [BB*MM];
__device__ float g_f0    [MM*DD];      // zf[0,1:] rows (asp)

// ---------------- reductions ----------------
__device__ __forceinline__ float bsum256(float v, float* red) {
    #pragma unroll
    for (int o = 16; o > 0; o >>= 1) v += __shfl_down_sync(0xffffffffu, v, o);
    if ((threadIdx.x & 31) == 0) red[threadIdx.x >> 5] = v;
    __syncthreads();
    if (threadIdx.x < 8) {
        v = red[threadIdx.x];
        #pragma unroll
        for (int o = 4; o > 0; o >>= 1) v += __shfl_down_sync(0xffu, v, o);
        if (threadIdx.x == 0) red[0] = v;
    }
    __syncthreads();
    float r = red[0];
    __syncthreads();
    return r;
}

__device__ __forceinline__ float bmax256(float v, float* red) {
    #pragma unroll
    for (int o = 16; o > 0; o >>= 1) v = fmaxf(v, __shfl_down_sync(0xffffffffu, v, o));
    if ((threadIdx.x & 31) == 0) red[threadIdx.x >> 5] = v;
    __syncthreads();
    if (threadIdx.x < 8) {
        v = red[threadIdx.x];
        #pragma unroll
        for (int o = 4; o > 0; o >>= 1) v = fmaxf(v, __shfl_down_sync(0xffu, v, o));
        if (threadIdx.x == 0) red[0] = v;
    }
    __syncthreads();
    float r = red[0];
    __syncthreads();
    return r;
}

// ---------------- k1: fused (weight-tiled dual GEMV) + WmdT transpose + copy ----------------
// Stages 32-column tiles of a row-major weight matrix into smem (coalesced LDG,
// conflict-free padded STS/LDS), each thread d dots its own weight row against
// 4 broadcast x-rows.
__device__ __forceinline__ void gemv_tiled(const float* __restrict__ W, int rs4, int co4,
                                           const float4* __restrict__ x4, float4* ws4,
                                           int d, float* a)
{
    const int row0 = threadIdx.x >> 3, c4 = threadIdx.x & 7;
    const float4* W4 = (const float4*)W;
    for (int tile = 0; tile < 8; tile++) {
        #pragma unroll
        for (int rr = 0; rr < 8; rr++) {
            const int row = rr*32 + row0;
            ws4[row*9 + c4] = W4[(size_t)row*rs4 + co4 + tile*8 + c4];
        }
        __syncthreads();
        #pragma unroll
        for (int kk4 = 0; kk4 < 8; kk4++) {
            const float4 wv = ws4[d*9 + kk4];
            const int kb = tile*8 + kk4;
            const float4 x0 = x4[kb], x1 = x4[64+kb], x2 = x4[128+kb], x3 = x4[192+kb];
            a[0]=fmaf(wv.x,x0.x,a[0]); a[0]=fmaf(wv.y,x0.y,a[0]); a[0]=fmaf(wv.z,x0.z,a[0]); a[0]=fmaf(wv.w,x0.w,a[0]);
            a[1]=fmaf(wv.x,x1.x,a[1]); a[1]=fmaf(wv.y,x1.y,a[1]); a[1]=fmaf(wv.z,x1.z,a[1]); a[1]=fmaf(wv.w,x1.w,a[1]);
            a[2]=fmaf(wv.x,x2.x,a[2]); a[2]=fmaf(wv.y,x2.y,a[2]); a[2]=fmaf(wv.z,x2.z,a[2]); a[2]=fmaf(wv.w,x2.w,a[2]);
            a[3]=fmaf(wv.x,x3.x,a[3]); a[3]=fmaf(wv.y,x3.y,a[3]); a[3]=fmaf(wv.z,x3.z,a[3]); a[3]=fmaf(wv.w,x3.w,a[3]);
        }
        __syncthreads();
    }
}

__global__ __launch_bounds__(256) void k1(const float* __restrict__ features,
                                          const float* __restrict__ Wz,
                                          const float* __restrict__ bz,
                                          const float* __restrict__ Wa,
                                          const float* __restrict__ Wm,
                                          float* __restrict__ out)
{
    __shared__ __align__(16) float xs[4][DD];
    __shared__ __align__(16) float fs[4][DD];
    __shared__ __align__(16) float4 ws4[DD*9];   // 36.9KB weight tile
    __shared__ float red[8];

    const int bid = blockIdx.x, tid = threadIdx.x;

    if (bid >= 128) {
        if (bid < 144) {
            // transpose Wm[:, 0:64] -> g_WmdT[e][d] via 32x32 smem tiles
            const int t = bid - 128;
            const int dtile = t >> 1, etile = t & 1;
            float* t32 = (float*)ws4;            // reuse smem
            const int r0 = tid >> 5, c = tid & 31;
            #pragma unroll
            for (int ii = 0; ii < 4; ii++) {
                int r = r0 + ii*8;
                t32[r*33 + c] = Wm[(size_t)(dtile*32 + r)*(DE+DD) + etile*32 + c];
            }
            __syncthreads();
            #pragma unroll
            for (int ii = 0; ii < 4; ii++) {
                int r = r0 + ii*8;
                g_WmdT[(etile*32 + r)*DD + dtile*32 + c] = t32[c*33 + r];
            }
        } else {
            // copy features -> out
            const int cb = bid - 144;
            const float4* src = (const float4*)features;
            float4* d4 = (float4*)out;
            const int total = BB*TP*DD/4;   // 32896
            for (int x = cb*256 + tid; x < total; x += 4*256) d4[x] = src[x];
        }
        return;
    }

    // ---- projection block: 4 token rows ----
    const int b = bid >> 6, m0 = (bid & 63) << 2;
    const int d = tid;

    {
        const int g = tid >> 6, q = tid & 63;
        ((float4*)xs[g])[q] = ((const float4*)&features[((size_t)b*TP + m0 + 1 + g)*DD])[q];
    }
    __syncthreads();

    // zf = x @ Wz^T + bz
    float a[4];
    { const float bzv = bz[d]; a[0]=bzv; a[1]=bzv; a[2]=bzv; a[3]=bzv; }
    gemv_tiled(Wz, DD/4, 0, (const float4*)xs, ws4, d, a);
    fs[0][d]=a[0]; fs[1][d]=a[1]; fs[2][d]=a[2]; fs[3][d]=a[3];
    __syncthreads();

    // nfdot[m] = f[m] . Wa[DE:DE+D]
    const float wnf = Wa[DE + d];
    #pragma unroll
    for (int m = 0; m < 4; m++) {
        float tot = bsum256(fs[m][d] * wnf, red);
        if (d == 0) g_nfdot[b*MM + m0 + m] = tot;
    }

    // batch-0 zf rows for k2 (asp)
    if (b == 0) {
        #pragma unroll
        for (int m = 0; m < 4; m++) g_f0[(m0 + m)*DD + d] = fs[m][d];
    }

    // nf_proj = f @ Wm_f^T   (Wm row stride 320 floats = 80 float4, col offset 64 = 16 float4)
    float p[4] = {0.f, 0.f, 0.f, 0.f};
    gemv_tiled(Wm, (DE+DD)/4, DE/4, (const float4*)fs, ws4, d, p);
    #pragma unroll
    for (int m = 0; m < 4; m++)
        g_nfproj[((size_t)b*MM + m0 + m)*DD + d] = p[m];
}

// ---------------- k2: sparse attention + message + output head ----------------
// grid 32 (b*16 + slot), 256 threads
__global__ __launch_bounds__(256) void k2(const float* __restrict__ dep,
                                          const int*   __restrict__ adj,
                                          const int*   __restrict__ asp_start,
                                          const int*   __restrict__ asp_end,
                                          const float* __restrict__ Wa,
                                          const float* __restrict__ Wh,
                                          float*       __restrict__ out)
{
    const int b    = blockIdx.x >> 4;
    const int slot = blockIdx.x & 15;
    const int st = asp_start[b];
    const int en = asp_end[b];
    const int i  = st + slot;
    if (i >= en || i >= MM) return;

    const int tid = threadIdx.x;

    __shared__ __align__(16) float w_s[2*MM];
    __shared__ __align__(16) int   list[2*MM];
    __shared__ __align__(16) float f0i[DD];
    __shared__ __align__(16) float wdep[DE];
    __shared__ __align__(16) float ds[64*DE];     // up to 64 dep rows per chunk (16KB)
    __shared__ __align__(16) float cat[2*DD];
    __shared__ float red[8];
    __shared__ int   cnt;

    if (tid == 0) cnt = 0;
    if (tid < DE) wdep[tid] = Wa[tid];
    f0i[tid] = g_f0[i*DD + tid];
    __syncthreads();

    // aspdot_i = asp[i] . Wa[DE+D:]
    const float aspdot_i = bsum256(f0i[tid] * Wa[DE + DD + tid], red);

    // ---- Phase A: masked scores, 2 candidates per thread ----
    float sv0 = -FLT_MAX, sv1 = -FLT_MAX;
    {
        const int msk = adj[((size_t)b*MM + i)*MM + tid];
        if (msk != 0) {
            int pos = atomicAdd(&cnt, 1); list[pos] = tid;
            const float4* dv4 = (const float4*)&dep[(((size_t)b*MM + i)*MM + tid)*DE];
            float s = 0.f;
            #pragma unroll
            for (int e4 = 0; e4 < 16; e4++) {
                const float4 v = dv4[e4];
                s = fmaf(v.x, wdep[4*e4+0], s); s = fmaf(v.y, wdep[4*e4+1], s);
                s = fmaf(v.z, wdep[4*e4+2], s); s = fmaf(v.w, wdep[4*e4+3], s);
            }
            s += g_nfdot[b*MM + tid] + aspdot_i;
            sv0 = (s > 0.f) ? s : 0.01f * s;
        }
    }
    {
        const int msk = adj[((size_t)b*MM + tid)*MM + i];
        if (msk != 0) {
            int pos = atomicAdd(&cnt, 1); list[pos] = tid + MM;
            const float4* dv4 = (const float4*)&dep[(((size_t)b*MM + tid)*MM + i)*DE];
            float s = 0.f;
            #pragma unroll
            for (int e4 = 0; e4 < 16; e4++) {
                const float4 v = dv4[e4];
                s = fmaf(v.x, wdep[4*e4+0], s); s = fmaf(v.y, wdep[4*e4+1], s);
                s = fmaf(v.z, wdep[4*e4+2], s); s = fmaf(v.w, wdep[4*e4+3], s);
            }
            s += g_nfdot[b*MM + tid] + aspdot_i;
            sv1 = (s > 0.f) ? s : 0.01f * s;
        }
    }
    __syncthreads();
    const int n = cnt;

    // ---- Phase B: softmax over valid keys ----
    const float smax = bmax256(fmaxf(sv0, sv1), red);
    const float e0 = (sv0 > -1e37f) ? expf(sv0 - smax) : 0.f;
    const float e1 = (sv1 > -1e37f) ? expf(sv1 - smax) : 0.f;
    w_s[tid] = e0; w_s[MM + tid] = e1;
    const float ssum = bsum256(e0 + e1, red);
    const float inv  = 1.f / ssum;

    // Wm_dep column for this d (registers; 256 threads -> 255-reg budget, no spill)
    const int d = tid;
    float wmd[DE];
    #pragma unroll
    for (int e = 0; e < DE; e++) wmd[e] = g_WmdT[e*DD + d];

    // ---- Phase C: fused[d] = sum_k w_k * relu(dep_k @ Wm_dep^T + nf_proj[k]) ----
    // Bulk-load all valid dep rows (chunks of 64) then crunch barrier-free.
    float acc = 0.f;
    float4* ds4 = (float4*)ds;
    for (int c0 = 0; c0 < n; c0 += 64) {
        const int nc = min(64, n - c0);
        __syncthreads();
        for (int idx = tid; idx < nc*16; idx += 256) {
            const int j = idx >> 4, e4 = idx & 15;
            const int kk = list[c0 + j];
            const int row = (kk < MM) ? i : (kk - MM);
            const int col = (kk < MM) ? kk : i;
            ds4[j*16 + e4] = ((const float4*)dep)[(((size_t)b*MM + row)*MM + col)*16 + e4];
        }
        __syncthreads();
        for (int j = 0; j < nc; j++) {
            const int kk = list[c0 + j];
            const float wk = w_s[kk] * inv;
            float m = g_nfproj[((size_t)b*MM + (kk & (MM-1)))*DD + d];
            #pragma unroll
            for (int e4 = 0; e4 < 16; e4++) {
                const float4 v = ds4[j*16 + e4];   // broadcast LDS
                m = fmaf(v.x, wmd[4*e4+0], m);
                m = fmaf(v.y, wmd[4*e4+1], m);
                m = fmaf(v.z, wmd[4*e4+2], m);
                m = fmaf(v.w, wmd[4*e4+3], m);
            }
            acc = fmaf(wk, fmaxf(m, 0.f), acc);
        }
    }

    // ---- Phase D: out[d] = relu( [fused, asp] . Wh_row_d ), warp-per-row dots ----
    cat[tid] = acc;
    cat[DD + tid] = f0i[tid];
    __syncthreads();

    const int w = tid >> 5, l = tid & 31;
    const float4* cat4 = (const float4*)cat;
    const float4 c0 = cat4[l], c1 = cat4[32+l], c2 = cat4[64+l], c3 = cat4[96+l];
    const size_t obase = ((size_t)b*TP + 1 + i)*DD;
    for (int dd = 0; dd < 32; dd++) {
        const int dr = w*32 + dd;
        const float4* r4 = (const float4*)(Wh + (size_t)dr*2*DD);
        const float4 w0 = r4[l], w1 = r4[32+l], w2 = r4[64+l], w3 = r4[96+l];
        float o = 0.f;
        o = fmaf(w0.x,c0.x,o); o = fmaf(w0.y,c0.y,o); o = fmaf(w0.z,c0.z,o); o = fmaf(w0.w,c0.w,o);
        o = fmaf(w1.x,c1.x,o); o = fmaf(w1.y,c1.y,o); o = fmaf(w1.z,c1.z,o); o = fmaf(w1.w,c1.w,o);
        o = fmaf(w2.x,c2.x,o); o = fmaf(w2.y,c2.y,o); o = fmaf(w2.z,c2.z,o); o = fmaf(w2.w,c2.w,o);
        o = fmaf(w3.x,c3.x,o); o = fmaf(w3.y,c3.y,o); o = fmaf(w3.z,c3.z,o); o = fmaf(w3.w,c3.w,o);
        #pragma unroll
        for (int off = 16; off > 0; off >>= 1) o += __shfl_down_sync(0xffffffffu, o, off);
        if (l == 0) out[obase + dr] = fmaxf(o, 0.f);
    }
}

// ---------------- launcher ----------------
extern "C" void kernel_launch(void* const* d_in, const int* in_sizes, int n_in,
                              void* d_out, int out_size)
{
    const float* features  = (const float*)d_in[0];
    const float* dep       = (const float*)d_in[1];
    const int*   adj       = (const int*)  d_in[2];
    const int*   asp_start = (const int*)  d_in[3];
    const int*   asp_end   = (const int*)  d_in[4];
    const float* Wz        = (const float*)d_in[5];
    const float* bz        = (const float*)d_in[6];
    const float* Wa        = (const float*)d_in[7];
    const float* Wm        = (const float*)d_in[8];
    const float* Wh        = (const float*)d_in[9];
    float* out = (float*)d_out;

    k1<<<148, 256>>>(features, Wz, bz, Wa, Wm, out);
    k2<<<32, 256>>>(dep, adj, asp_start, asp_end, Wa, Wh, out);
}

// round 6
// speedup vs baseline: 2.1458x; 1.1728x over previous
#include <cuda_runtime.h>
#include <math.h>
#include <float.h>

#define BB 2
#define MM 256
#define DD 256
#define DE 64
#define TP 257
#define WM_RS 320   // Wm row stride in floats (DE + DD)

typedef unsigned long long u64;

// ---------------- f32x2 packed helpers ----------------
__device__ __forceinline__ u64 ffma2(u64 a, u64 b, u64 c) {
    u64 d;
    asm("fma.rn.f32x2 %0, %1, %2, %3;" : "=l"(d) : "l"(a), "l"(b), "l"(c));
    return d;
}
__device__ __forceinline__ u64 fadd2(u64 a, u64 b) {
    u64 d;
    asm("add.rn.f32x2 %0, %1, %2;" : "=l"(d) : "l"(a), "l"(b));
    return d;
}
__device__ __forceinline__ u64 pack2(float lo, float hi) {
    u64 p;
    asm("mov.b64 %0, {%1, %2};" : "=l"(p) : "f"(lo), "f"(hi));
    return p;
}
__device__ __forceinline__ float2 unpack2(u64 p) {
    float2 r;
    asm("mov.b64 {%0, %1}, %2;" : "=f"(r.x), "=f"(r.y) : "l"(p));
    return r;
}

// ---------------- scratch ----------------
__device__ float g_nfproj[BB*MM*DD];
__device__ float g_nfdot [BB*MM];
__device__ float g_f0    [MM*DD];          // zf[0,1:] rows (asp)
__device__ float g_fused [BB*16*DD];       // fused message per query

// ---------------- reductions (256 threads) ----------------
__device__ __forceinline__ float bsum256(float v, float* red) {
    #pragma unroll
    for (int o = 16; o > 0; o >>= 1) v += __shfl_down_sync(0xffffffffu, v, o);
    if ((threadIdx.x & 31) == 0) red[threadIdx.x >> 5] = v;
    __syncthreads();
    if (threadIdx.x < 8) {
        v = red[threadIdx.x];
        #pragma unroll
        for (int o = 4; o > 0; o >>= 1) v += __shfl_down_sync(0xffu, v, o);
        if (threadIdx.x == 0) red[0] = v;
    }
    __syncthreads();
    float r = red[0];
    __syncthreads();
    return r;
}

__device__ __forceinline__ float bmax256(float v, float* red) {
    #pragma unroll
    for (int o = 16; o > 0; o >>= 1) v = fmaxf(v, __shfl_down_sync(0xffffffffu, v, o));
    if ((threadIdx.x & 31) == 0) red[threadIdx.x >> 5] = v;
    __syncthreads();
    if (threadIdx.x < 8) {
        v = red[threadIdx.x];
        #pragma unroll
        for (int o = 4; o > 0; o >>= 1) v = fmaxf(v, __shfl_down_sync(0xffu, v, o));
        if (threadIdx.x == 0) red[0] = v;
    }
    __syncthreads();
    float r = red[0];
    __syncthreads();
    return r;
}

// ---------------- k1: 8-row projection blocks with f32x2 ----------------
__device__ __forceinline__ void mat8(const float4* __restrict__ W4, int rs4, int co4,
                                     const float (*xT)[8], float4* ws4, int d,
                                     u64* acc)
{
    const int tid = threadIdx.x;
    for (int t = 0; t < 8; t++) {
        #pragma unroll
        for (int rr = 0; rr < 8; rr++) {
            const int row = rr*32 + (tid >> 3);
            ws4[row*9 + (tid & 7)] = W4[(size_t)row*rs4 + co4 + t*8 + (tid & 7)];
        }
        __syncthreads();
        #pragma unroll
        for (int k4 = 0; k4 < 8; k4++) {
            const float4 wv = ws4[d*9 + k4];
            const int kb = t*32 + k4*4;
            #pragma unroll
            for (int j = 0; j < 4; j++) {
                const float w = (j == 0) ? wv.x : (j == 1) ? wv.y : (j == 2) ? wv.z : wv.w;
                const u64 wp = pack2(w, w);
                const ulonglong2 xa = *(const ulonglong2*)&xT[kb + j][0];
                const ulonglong2 xb = *(const ulonglong2*)&xT[kb + j][4];
                acc[0] = ffma2(xa.x, wp, acc[0]);
                acc[1] = ffma2(xa.y, wp, acc[1]);
                acc[2] = ffma2(xb.x, wp, acc[2]);
                acc[3] = ffma2(xb.y, wp, acc[3]);
            }
        }
        __syncthreads();
    }
}

__global__ __launch_bounds__(256) void k1(const float* __restrict__ features,
                                          const float* __restrict__ Wz,
                                          const float* __restrict__ bz,
                                          const float* __restrict__ Wa,
                                          const float* __restrict__ Wm,
                                          float* __restrict__ out)
{
    __shared__ __align__(16) float  xT[DD][8];    // x^T, then zf^T  (8KB)
    __shared__ __align__(16) float4 ws4[DD*9];    // weight tile     (36.9KB)

    const int bid = blockIdx.x, tid = threadIdx.x;

    if (bid >= 64) {
        // copy features -> out (16 blocks)
        const int cb = bid - 64;
        const float4* src = (const float4*)features;
        float4* d4 = (float4*)out;
        const int total = BB*TP*DD/4;   // 32896
        for (int x = cb*256 + tid; x < total; x += 16*256) d4[x] = src[x];
        return;
    }

    const int b = bid >> 5, m0 = (bid & 31) << 3;
    const int d = tid;

    // build x^T : xT[k][r] = features[b, 1+m0+r, k]
    #pragma unroll
    for (int r = 0; r < 8; r++)
        xT[tid][r] = features[((size_t)b*TP + 1 + m0 + r)*DD + tid];
    __syncthreads();

    // ---- mat1: zf = x @ Wz^T + bz ----
    u64 acc[4];
    { const float bzv = bz[d]; const u64 bp = pack2(bzv, bzv);
      acc[0]=bp; acc[1]=bp; acc[2]=bp; acc[3]=bp; }
    mat8((const float4*)Wz, DD/4, 0, xT, ws4, d, acc);

    float zf[8];
    #pragma unroll
    for (int p = 0; p < 4; p++) {
        const float2 f2 = unpack2(acc[p]);
        zf[2*p] = f2.x; zf[2*p + 1] = f2.y;
    }

    // overwrite xT with zf^T; products into ws4 area for nfdot reduce
    float* pr = (float*)ws4;
    const float wnf = Wa[DE + d];
    #pragma unroll
    for (int r = 0; r < 8; r++) {
        xT[d][r] = zf[r];
        pr[r*DD + d] = zf[r] * wnf;
    }
    if (b == 0) {
        #pragma unroll
        for (int r = 0; r < 8; r++) g_f0[(m0 + r)*DD + d] = zf[r];
    }
    __syncthreads();

    // warp m reduces pr[m][*] -> nfdot
    {
        const int m = tid >> 5, lane = tid & 31;
        float s = 0.f;
        #pragma unroll
        for (int qch = 0; qch < 8; qch++) s += pr[m*DD + lane + qch*32];
        #pragma unroll
        for (int o = 16; o > 0; o >>= 1) s += __shfl_down_sync(0xffffffffu, s, o);
        if (lane == 0) g_nfdot[b*MM + m0 + m] = s;
    }
    __syncthreads();

    // ---- mat2: nfproj = zf @ Wm_f^T ----
    acc[0]=0; acc[1]=0; acc[2]=0; acc[3]=0;
    mat8((const float4*)Wm, WM_RS/4, DE/4, xT, ws4, d, acc);

    #pragma unroll
    for (int p = 0; p < 4; p++) {
        const float2 f2 = unpack2(acc[p]);
        g_nfproj[((size_t)b*MM + m0 + 2*p    )*DD + d] = f2.x;
        g_nfproj[((size_t)b*MM + m0 + 2*p + 1)*DD + d] = f2.y;
    }
}

// ---------------- k2b: scores + softmax + message (per d-chunk) ----------------
// grid (4 dchunks, 32 queries), 256 threads
__global__ __launch_bounds__(256) void k2b(const float* __restrict__ dep,
                                           const int*   __restrict__ adj,
                                           const int*   __restrict__ asp_start,
                                           const float* __restrict__ Wa,
                                           const float* __restrict__ Wm)
{
    const int dc = blockIdx.x;          // 0..3
    const int q  = blockIdx.y;          // 0..31
    const int b  = q >> 4, slot = q & 15;
    const int i  = asp_start[b] + slot;

    const int tid = threadIdx.x;

    __shared__ __align__(16) float dsr[96][68];   // staged dep rows (25.5KB)
    __shared__ float s_l[2*MM];
    __shared__ float wn [2*MM];
    __shared__ int   list[2*MM];
    __shared__ float wdep[DE];
    __shared__ float fpart[4][64];
    __shared__ float red[8];
    __shared__ int   cnt;

    if (tid == 0) cnt = 0;
    if (tid < DE) wdep[tid] = Wa[tid];
    __syncthreads();

    // aspdot
    const float aspdot = bsum256(g_f0[i*DD + tid] * Wa[DE + DD + tid], red);

    // candidate scan (2 per thread)
    if (adj[((size_t)b*MM + i)*MM + tid] != 0) {
        int p = atomicAdd(&cnt, 1); list[p] = tid;
    }
    if (adj[((size_t)b*MM + tid)*MM + i] != 0) {
        int p = atomicAdd(&cnt, 1); list[p] = tid + MM;
    }
    __syncthreads();
    const int n = cnt;

    // ---- scores (chunked staging) ----
    for (int c0 = 0; c0 < n; c0 += 96) {
        const int nc = min(96, n - c0);
        __syncthreads();
        for (int idx = tid; idx < nc*16; idx += 256) {
            const int j = idx >> 4, e4 = idx & 15;
            const int kk = list[c0 + j];
            const int row = (kk < MM) ? i : (kk - MM);
            const int col = (kk < MM) ? kk : i;
            *(float4*)&dsr[j][e4*4] =
                ((const float4*)dep)[(((size_t)b*MM + row)*MM + col)*16 + e4];
        }
        __syncthreads();
        for (int j = tid; j < nc; j += 256) {
            float s = 0.f;
            #pragma unroll
            for (int e4 = 0; e4 < 16; e4++) {
                const float4 v = *(const float4*)&dsr[j][e4*4];
                s = fmaf(v.x, wdep[4*e4+0], s); s = fmaf(v.y, wdep[4*e4+1], s);
                s = fmaf(v.z, wdep[4*e4+2], s); s = fmaf(v.w, wdep[4*e4+3], s);
            }
            const int kk = list[c0 + j];
            s += g_nfdot[b*MM + (kk & (MM-1))] + aspdot;
            s_l[c0 + j] = (s > 0.f) ? s : 0.01f * s;
        }
    }
    __syncthreads();

    // ---- softmax over n positions ----
    const float sv0 = (tid       < n) ? s_l[tid]       : -FLT_MAX;
    const float sv1 = (tid + 256 < n) ? s_l[tid + 256] : -FLT_MAX;
    const float smax = bmax256(fmaxf(sv0, sv1), red);
    const float e0 = (tid       < n) ? expf(sv0 - smax) : 0.f;
    const float e1 = (tid + 256 < n) ? expf(sv1 - smax) : 0.f;
    if (tid       < n) wn[tid]       = e0;
    if (tid + 256 < n) wn[tid + 256] = e1;
    const float inv = 1.f / bsum256(e0 + e1, red);

    // ---- message: thread (kg, dl), d = dc*64+dl ----
    const int kg = tid >> 6, dl = tid & 63;
    const int d  = dc*64 + dl;

    // Wm_dep row d as 32 f32x2 packs (one-time, L2)
    u64 wp[32];
    {
        const ulonglong2* w2 = (const ulonglong2*)(Wm + (size_t)d*WM_RS);
        #pragma unroll
        for (int t2 = 0; t2 < 16; t2++) {
            const ulonglong2 v = w2[t2];
            wp[2*t2] = v.x; wp[2*t2 + 1] = v.y;
        }
    }

    float acc = 0.f;
    for (int c0 = 0; c0 < n; c0 += 96) {
        const int nc = min(96, n - c0);
        __syncthreads();
        for (int idx = tid; idx < nc*16; idx += 256) {
            const int j = idx >> 4, e4 = idx & 15;
            const int kk = list[c0 + j];
            const int row = (kk < MM) ? i : (kk - MM);
            const int col = (kk < MM) ? kk : i;
            *(float4*)&dsr[j][e4*4] =
                ((const float4*)dep)[(((size_t)b*MM + row)*MM + col)*16 + e4];
        }
        __syncthreads();
        for (int jl = kg; jl < nc; jl += 4) {
            const int pos = c0 + jl;
            const int kk  = list[pos];
            const float wk = wn[pos] * inv;
            const float mi = g_nfproj[((size_t)b*MM + (kk & (MM-1)))*DD + d];
            const ulonglong2* dr2 = (const ulonglong2*)&dsr[jl][0];
            // full 64-deep dot: 16 ulonglong2 = 64 floats (round-5 bug: stopped at 8)
            u64 mA = 0, mB = 0, mC = 0, mD = 0;
            #pragma unroll
            for (int t2 = 0; t2 < 16; t2 += 2) {
                const ulonglong2 v0 = dr2[t2];
                const ulonglong2 v1 = dr2[t2 + 1];
                mA = ffma2(v0.x, wp[2*t2],     mA);
                mB = ffma2(v0.y, wp[2*t2 + 1], mB);
                mC = ffma2(v1.x, wp[2*t2 + 2], mC);
                mD = ffma2(v1.y, wp[2*t2 + 3], mD);
            }
            const u64 mS = fadd2(fadd2(mA, mB), fadd2(mC, mD));
            const float2 ms = unpack2(mS);
            const float mval = mi + ms.x + ms.y;
            acc = fmaf(wk, fmaxf(mval, 0.f), acc);
        }
    }

    fpart[kg][dl] = acc;
    __syncthreads();
    if (tid < 64)
        g_fused[q*DD + dc*64 + tid] =
            fpart[0][tid] + fpart[1][tid] + fpart[2][tid] + fpart[3][tid];
}

// ---------------- k2c: output head ----------------
// grid 256 = (32 q × 8 rowgroups); 256 threads = 32 Wh rows × 8 lanes
__global__ __launch_bounds__(256) void k2c(const int*   __restrict__ asp_start,
                                           const float* __restrict__ Wh,
                                           float*       __restrict__ out)
{
    const int q  = blockIdx.x >> 3;
    const int rg = blockIdx.x & 7;
    const int b  = q >> 4, slot = q & 15;
    const int i  = asp_start[b] + slot;

    const int tid = threadIdx.x;

    __shared__ __align__(16) float cat[2*DD];
    cat[tid]      = g_fused[q*DD + tid];
    cat[DD + tid] = g_f0[i*DD + tid];
    __syncthreads();

    const int warp = tid >> 5, lane = tid & 31;
    const int rsub = lane >> 3, l8 = lane & 7;
    const int dr = rg*32 + warp*4 + rsub;

    const ulonglong2* wrow = (const ulonglong2*)(Wh + (size_t)dr*2*DD);
    const ulonglong2* cat2 = (const ulonglong2*)cat;

    u64 oA = 0, oB = 0;
    #pragma unroll
    for (int t = 0; t < 16; t++) {
        const int idx = t*8 + l8;
        const ulonglong2 wv = wrow[idx];
        const ulonglong2 cv = cat2[idx];
        oA = ffma2(wv.x, cv.x, oA);
        oB = ffma2(wv.y, cv.y, oB);
    }
    const float2 a = unpack2(oA), bb = unpack2(oB);
    float o = (a.x + a.y) + (bb.x + bb.y);
    o += __shfl_down_sync(0xffffffffu, o, 4, 8);
    o += __shfl_down_sync(0xffffffffu, o, 2, 8);
    o += __shfl_down_sync(0xffffffffu, o, 1, 8);
    if (l8 == 0)
        out[((size_t)b*TP + 1 + i)*DD + dr] = fmaxf(o, 0.f);
}

// ---------------- launcher ----------------
extern "C" void kernel_launch(void* const* d_in, const int* in_sizes, int n_in,
                              void* d_out, int out_size)
{
    const float* features  = (const float*)d_in[0];
    const float* dep       = (const float*)d_in[1];
    const int*   adj       = (const int*)  d_in[2];
    const int*   asp_start = (const int*)  d_in[3];
    const float* Wz        = (const float*)d_in[5];
    const float* bz        = (const float*)d_in[6];
    const float* Wa        = (const float*)d_in[7];
    const float* Wm        = (const float*)d_in[8];
    const float* Wh        = (const float*)d_in[9];
    float* out = (float*)d_out;

    k1 <<<80, 256>>>(features, Wz, bz, Wa, Wm, out);
    k2b<<<dim3(4, 32), 256>>>(dep, adj, asp_start, Wa, Wm);
    k2c<<<256, 256>>>(asp_start, Wh, out);
}